// round 1
// baseline (speedup 1.0000x reference)
#include <cuda_runtime.h>
#include <cuda_bf16.h>

#define N_NODES 50000
#define N_EDGES 800000
#define HEADS 8
#define DOUT 32
#define HD 256          // HEADS*DOUT == IN_FEATS == 256
#define NEG_SLOPE 0.2f

// ---------------- scratch (static device globals; no allocation) -------------
__device__ float g_h [N_NODES * HD];      // projected node features (N,256)
__device__ float g_el[N_NODES * HEADS];   // per-node left attention scalar
__device__ float g_er[N_NODES * HEADS];   // per-node right attention scalar
__device__ float g_s [N_NODES * HEADS];   // softmax denominators
__device__ float g_P [N_EDGES * HEADS];   // per-edge exp(logit)
__device__ float g_C [HEADS * HEADS];     // folded W_e * attn_e  (k-major: C[k*8+h])

// ---------------- K0: fold W_e (8,256) with attn_e (8,32) -> C (8,8) ---------
__global__ void k0_foldC(const float* __restrict__ W_e, const float* __restrict__ attn_e) {
    int t = threadIdx.x;
    if (t < 64) {
        int k = t >> 3, h = t & 7;
        float s = 0.f;
        #pragma unroll
        for (int d = 0; d < DOUT; ++d)
            s += W_e[k * HD + h * DOUT + d] * attn_e[h * DOUT + d];
        g_C[k * 8 + h] = s;
    }
}

// ---------------- K1: SGEMM  h = feat(50000,256) @ W_src(256,256) ------------
// 128x128 block tile, BK=16, 256 threads, 8x8 microtile.
__global__ __launch_bounds__(256) void k1_gemm(const float* __restrict__ A,
                                               const float* __restrict__ B) {
    __shared__ float As[16][128];   // [k][m]
    __shared__ float Bs[16][128];   // [k][n]
    const int t  = threadIdx.x;
    const int tx = t & 15;          // col group
    const int ty = t >> 4;          // row group
    const int bm = blockIdx.x * 128;
    const int bn = blockIdx.y * 128;

    float acc[8][8];
    #pragma unroll
    for (int i = 0; i < 8; ++i)
        #pragma unroll
        for (int j = 0; j < 8; ++j) acc[i][j] = 0.f;

    for (int k0 = 0; k0 < HD; k0 += 16) {
        #pragma unroll
        for (int l = 0; l < 2; ++l) {
            int f = t + l * 256;            // float4 index 0..511
            // A tile: 128 rows x 16 k
            int arow = f >> 2;
            int kin  = (f & 3) * 4;
            int grow = bm + arow;
            float4 va = make_float4(0.f, 0.f, 0.f, 0.f);
            if (grow < N_NODES)
                va = *(const float4*)(A + (long)grow * HD + k0 + kin);
            As[kin + 0][arow] = va.x;
            As[kin + 1][arow] = va.y;
            As[kin + 2][arow] = va.z;
            As[kin + 3][arow] = va.w;
            // B tile: 16 k x 128 n
            int krow = f >> 5;
            int ncol = (f & 31) * 4;
            *(float4*)(&Bs[krow][ncol]) =
                *(const float4*)(B + (long)(k0 + krow) * HD + bn + ncol);
        }
        __syncthreads();

        #pragma unroll
        for (int k = 0; k < 16; ++k) {
            float a8[8], b8[8];
            *(float4*)(a8)     = *(const float4*)(&As[k][ty * 8]);
            *(float4*)(a8 + 4) = *(const float4*)(&As[k][ty * 8 + 4]);
            *(float4*)(b8)     = *(const float4*)(&Bs[k][tx * 8]);
            *(float4*)(b8 + 4) = *(const float4*)(&Bs[k][tx * 8 + 4]);
            #pragma unroll
            for (int i = 0; i < 8; ++i)
                #pragma unroll
                for (int j = 0; j < 8; ++j)
                    acc[i][j] += a8[i] * b8[j];
        }
        __syncthreads();
    }

    #pragma unroll
    for (int i = 0; i < 8; ++i) {
        int row = bm + ty * 8 + i;
        if (row < N_NODES) {
            float* o = g_h + (long)row * HD + bn + tx * 8;
            *(float4*)(o)     = make_float4(acc[i][0], acc[i][1], acc[i][2], acc[i][3]);
            *(float4*)(o + 4) = make_float4(acc[i][4], acc[i][5], acc[i][6], acc[i][7]);
        }
    }
}

// ---------------- K2: per-node el/er, zero s, out = bias ---------------------
// one warp per node; lane handles 8 contiguous floats (head = lane/4)
__global__ __launch_bounds__(256) void k2_node(const float* __restrict__ attn_l,
                                               const float* __restrict__ attn_r,
                                               const float* __restrict__ bias,
                                               float* __restrict__ out) {
    __shared__ float sal[HD], sar[HD], sb[HD];
    int t = threadIdx.x;
    sal[t] = attn_l[t];
    sar[t] = attn_r[t];
    sb[t]  = bias[t];
    __syncthreads();

    int warp = t >> 5, lane = t & 31;
    int n = blockIdx.x * 8 + warp;
    if (n >= N_NODES) return;

    const float4* hp = (const float4*)(g_h + (long)n * HD);
    float4 v0 = hp[lane * 2], v1 = hp[lane * 2 + 1];
    float4 a0 = ((const float4*)sal)[lane * 2], a1 = ((const float4*)sal)[lane * 2 + 1];
    float4 r0 = ((const float4*)sar)[lane * 2], r1 = ((const float4*)sar)[lane * 2 + 1];

    float el = v0.x*a0.x + v0.y*a0.y + v0.z*a0.z + v0.w*a0.w
             + v1.x*a1.x + v1.y*a1.y + v1.z*a1.z + v1.w*a1.w;
    float er = v0.x*r0.x + v0.y*r0.y + v0.z*r0.z + v0.w*r0.w
             + v1.x*r1.x + v1.y*r1.y + v1.z*r1.z + v1.w*r1.w;
    // reduce across the 4 lanes of each head group
    el += __shfl_xor_sync(0xffffffffu, el, 1);
    el += __shfl_xor_sync(0xffffffffu, el, 2);
    er += __shfl_xor_sync(0xffffffffu, er, 1);
    er += __shfl_xor_sync(0xffffffffu, er, 2);
    if ((lane & 3) == 0) {
        g_el[n * HEADS + (lane >> 2)] = el;
        g_er[n * HEADS + (lane >> 2)] = er;
    }
    if (lane < HEADS) g_s[n * HEADS + lane] = 0.f;

    float4* op = (float4*)(out + (long)n * HD);
    op[lane * 2]     = ((const float4*)sb)[lane * 2];
    op[lane * 2 + 1] = ((const float4*)sb)[lane * 2 + 1];
}

// ---------------- K3: per-edge p = exp(leakyrelu(el+er+ee)); s += p ----------
__global__ __launch_bounds__(256) void k3_edge(const float* __restrict__ edge_emb,
                                               const int* __restrict__ src,
                                               const int* __restrict__ dst) {
    __shared__ float Cs[64];
    int t = threadIdx.x;
    if (t < 64) Cs[t] = g_C[t];
    __syncthreads();

    int e = blockIdx.x * blockDim.x + t;
    if (e >= N_EDGES) return;

    int se = src[e], de = dst[e];
    const float4* ep = (const float4*)(edge_emb + (long)e * HEADS);
    float4 e0 = ep[0], e1 = ep[1];
    float ein[8] = {e0.x, e0.y, e0.z, e0.w, e1.x, e1.y, e1.z, e1.w};

    float4 l0 = *(const float4*)(g_el + se * HEADS);
    float4 l1 = *(const float4*)(g_el + se * HEADS + 4);
    float4 r0 = *(const float4*)(g_er + de * HEADS);
    float4 r1 = *(const float4*)(g_er + de * HEADS + 4);
    float elv[8] = {l0.x, l0.y, l0.z, l0.w, l1.x, l1.y, l1.z, l1.w};
    float erv[8] = {r0.x, r0.y, r0.z, r0.w, r1.x, r1.y, r1.z, r1.w};

    float pv[8];
    #pragma unroll
    for (int h = 0; h < 8; ++h) {
        float ee = 0.f;
        #pragma unroll
        for (int k = 0; k < 8; ++k) ee += ein[k] * Cs[k * 8 + h];
        float x = elv[h] + erv[h] + ee;
        x = (x > 0.f) ? x : NEG_SLOPE * x;
        float p = __expf(x);
        pv[h] = p;
        atomicAdd(&g_s[de * HEADS + h], p);
    }
    float4* pp = (float4*)(g_P + (long)e * HEADS);
    pp[0] = make_float4(pv[0], pv[1], pv[2], pv[3]);
    pp[1] = make_float4(pv[4], pv[5], pv[6], pv[7]);
}

// ---------------- K4: weighted aggregation via vector reductions -------------
__device__ __forceinline__ void red_add_v4(float* addr, float a, float b, float c, float d) {
    asm volatile("red.global.add.v4.f32 [%0], {%1, %2, %3, %4};"
                 :: "l"(addr), "f"(a), "f"(b), "f"(c), "f"(d) : "memory");
}

// one warp per edge; lane handles 8 contiguous floats (head = lane/4)
__global__ __launch_bounds__(256) void k4_agg(const int* __restrict__ src,
                                              const int* __restrict__ dst,
                                              float* __restrict__ out) {
    int t = threadIdx.x, warp = t >> 5, lane = t & 31;
    int e = blockIdx.x * 8 + warp;
    if (e >= N_EDGES) return;

    int se = __ldg(&src[e]);
    int de = __ldg(&dst[e]);

    float a = 0.f;
    if (lane < HEADS)
        a = g_P[(long)e * HEADS + lane] / (g_s[de * HEADS + lane] + 1e-9f);
    float alpha = __shfl_sync(0xffffffffu, a, lane >> 2);

    const float4* hp = (const float4*)(g_h + (long)se * HD);
    float4 x = hp[lane * 2];
    float4 y = hp[lane * 2 + 1];

    float* op = out + (long)de * HD + lane * 8;
    red_add_v4(op,     alpha * x.x, alpha * x.y, alpha * x.z, alpha * x.w);
    red_add_v4(op + 4, alpha * y.x, alpha * y.y, alpha * y.z, alpha * y.w);
}

// ---------------- launch ------------------------------------------------------
extern "C" void kernel_launch(void* const* d_in, const int* in_sizes, int n_in,
                              void* d_out, int out_size) {
    const float* feat     = (const float*)d_in[0];
    const float* edge_emb = (const float*)d_in[1];
    const int*   src      = (const int*)  d_in[2];
    const int*   dst      = (const int*)  d_in[3];
    const float* W_src    = (const float*)d_in[4];
    const float* W_e      = (const float*)d_in[5];
    const float* attn_l   = (const float*)d_in[6];
    const float* attn_r   = (const float*)d_in[7];
    const float* attn_e   = (const float*)d_in[8];
    const float* bias     = (const float*)d_in[9];
    float* out = (float*)d_out;

    k0_foldC<<<1, 64>>>(W_e, attn_e);

    dim3 g1((N_NODES + 127) / 128, 2);
    k1_gemm<<<g1, 256>>>(feat, W_src);

    k2_node<<<(N_NODES + 7) / 8, 256>>>(attn_l, attn_r, bias, out);

    k3_edge<<<(N_EDGES + 255) / 256, 256>>>(edge_emb, src, dst);

    k4_agg<<<(N_EDGES + 7) / 8, 256>>>(src, dst, out);
}